// round 14
// baseline (speedup 1.0000x reference)
#include <cuda_runtime.h>
#include <math.h>

#define NN     8192
#define TILE   64
#define NBLK   (NN / TILE)                 // 128
#define NPAIRS (NBLK * (NBLK + 1) / 2)     // 8256

// Deterministic partial rowsums: g_partial[slot][row], each (row,slot) written
// exactly once per launch (no atomics -> bit-identical every call).
__device__ float g_partial[(size_t)NBLK * NN];   // 4 MB scratch
__device__ float g_rinv[NN];

// Map linear pair index p -> (bi, bj) with bi <= bj.
// offset(bi) = bi*(2*NBLK+1-bi)/2
__device__ __forceinline__ void decode_pair(int p, int& bi, int& bj) {
    const int C = 2 * NBLK + 1;                       // 257
    float disc = (float)(C * C - 8 * p);
    int x = (int)(((float)C - sqrtf(disc)) * 0.5f);
    if (x < 0) x = 0;
    while (x > 0 && x * (C - x) / 2 > p) x--;
    while ((x + 1) * (C - (x + 1)) / 2 <= p) x++;
    bi = x;
    bj = bi + (p - bi * (C - bi) / 2);
}

// ---------------------------------------------------------------------------
// Pass 1: per-tile-pair rowsums of s = relu((A + A^T)/2).
// For pair (bi,bj): row sums of the tile go to slot bj (rows of block bi);
// by symmetry the column sums are the row sums of block bj's rows -> slot bi.
// ---------------------------------------------------------------------------
__global__ __launch_bounds__(256) void rowsum_kernel(const float* __restrict__ A) {
    __shared__ float trs[TILE][TILE + 1];   // A[bj-tile][bi-tile], transposed
    __shared__ float rowpart[2][TILE];
    __shared__ float colbuf[4][TILE];

    int bi, bj;
    decode_pair(blockIdx.x, bi, bj);
    const int tx = threadIdx.x;   // 0..63 (column within tile)
    const int ty = threadIdx.y;   // 0..3
    const int gi0 = bi * TILE, gj0 = bj * TILE;

    // Load lower tile A[gj0+r][gi0+c] transposed into smem (coalesced loads,
    // stride-65 stores -> conflict-free).
    #pragma unroll
    for (int k = 0; k < 16; k++) {
        int r = ty * 16 + k;
        trs[tx][r] = A[(size_t)(gj0 + r) * NN + (gi0 + tx)];
    }
    __syncthreads();

    float csum = 0.0f;  // column sum for column tx (this thread's 16 rows)
    #pragma unroll
    for (int k = 0; k < 16; k++) {
        int i = ty * 16 + k;
        float a = A[(size_t)(gi0 + i) * NN + (gj0 + tx)];     // A[gi][gj]
        float b = trs[i][tx];                                 // A[gj][gi]
        float s = fmaxf(0.5f * (a + b), 0.0f);
        csum += s;
        // Row reduction across the 32 lanes of this warp (fixed i per warp).
        float rs = s;
        rs += __shfl_down_sync(0xffffffffu, rs, 16);
        rs += __shfl_down_sync(0xffffffffu, rs, 8);
        rs += __shfl_down_sync(0xffffffffu, rs, 4);
        rs += __shfl_down_sync(0xffffffffu, rs, 2);
        rs += __shfl_down_sync(0xffffffffu, rs, 1);
        if ((tx & 31) == 0) rowpart[tx >> 5][i] = rs;
    }
    colbuf[ty][tx] = csum;
    __syncthreads();

    if (ty == 0) {
        // row sums for rows gi0..gi0+63 -> slot bj (coalesced store)
        g_partial[(size_t)bj * NN + gi0 + tx] = rowpart[0][tx] + rowpart[1][tx];
    } else if (ty == 1 && bi != bj) {
        // column sums == row sums for rows gj0..gj0+63 -> slot bi
        g_partial[(size_t)bi * NN + gj0 + tx] =
            colbuf[0][tx] + colbuf[1][tx] + colbuf[2][tx] + colbuf[3][tx];
    }
}

// ---------------------------------------------------------------------------
// Pass 2: rowsum = 1 (self-loop) + sum of 128 partials; r_inv = rsqrt(rowsum).
// rowsum >= 1 always, so no inf handling needed.
// ---------------------------------------------------------------------------
__global__ void rinv_kernel() {
    int i = blockIdx.x * blockDim.x + threadIdx.x;
    float acc = 1.0f;
    #pragma unroll 8
    for (int s = 0; s < NBLK; s++)
        acc += g_partial[(size_t)s * NN + i];   // coalesced across threads
    g_rinv[i] = rsqrtf(acc);
}

// ---------------------------------------------------------------------------
// Pass 3: out[i][j] = r_inv[i] * (s + (i==j)) * r_inv[j], upper tile written
// directly, mirrored tile written via smem transpose (both fully coalesced).
// ---------------------------------------------------------------------------
__global__ __launch_bounds__(256) void scale_kernel(const float* __restrict__ A,
                                                    float* __restrict__ out) {
    __shared__ float trs[TILE][TILE + 1];
    __shared__ float sot[TILE][TILE + 1];
    __shared__ float rinv_i[TILE];
    __shared__ float rinv_j[TILE];

    int bi, bj;
    decode_pair(blockIdx.x, bi, bj);
    const int tx = threadIdx.x;
    const int ty = threadIdx.y;
    const int gi0 = bi * TILE, gj0 = bj * TILE;

    if (ty == 0) rinv_i[tx] = g_rinv[gi0 + tx];
    if (ty == 1) rinv_j[tx] = g_rinv[gj0 + tx];

    #pragma unroll
    for (int k = 0; k < 16; k++) {
        int r = ty * 16 + k;
        trs[tx][r] = A[(size_t)(gj0 + r) * NN + (gi0 + tx)];
    }
    __syncthreads();

    const float rj = rinv_j[tx];
    #pragma unroll
    for (int k = 0; k < 16; k++) {
        int i = ty * 16 + k;
        float a = A[(size_t)(gi0 + i) * NN + (gj0 + tx)];
        float s = fmaxf(0.5f * (a + trs[i][tx]), 0.0f);
        if (gi0 + i == gj0 + tx) s += 1.0f;        // self-loop on the diagonal
        float v = rinv_i[i] * s * rj;
        out[(size_t)(gi0 + i) * NN + (gj0 + tx)] = v;
        sot[i][tx] = v;
    }

    if (bi != bj) {
        __syncthreads();
        #pragma unroll
        for (int k = 0; k < 16; k++) {
            int r = ty * 16 + k;
            out[(size_t)(gj0 + r) * NN + (gi0 + tx)] = sot[tx][r];
        }
    }
}

extern "C" void kernel_launch(void* const* d_in, const int* in_sizes, int n_in,
                              void* d_out, int out_size) {
    const float* A = (const float*)d_in[0];
    float* out = (float*)d_out;

    dim3 blk(64, 4);
    rowsum_kernel<<<NPAIRS, blk>>>(A);
    rinv_kernel<<<NN / 256, 256>>>();
    scale_kernel<<<NPAIRS, blk>>>(A, out);
}

// round 15
// speedup vs baseline: 1.3203x; 1.3203x over previous
#include <cuda_runtime.h>
#include <math.h>

#define NN     8192
#define TILE   64
#define NBLK   (NN / TILE)                 // 128
#define NPAIRS (NBLK * (NBLK + 1) / 2)     // 8256
#define PAD    65                          // conflict-free dual-orientation access

// Deterministic partial rowsums: g_partial[slot][row], each (row,slot) written
// exactly once per launch (no atomics -> bit-identical every call).
__device__ float g_partial[(size_t)NBLK * NN];   // 4 MB scratch
__device__ float g_rinv[NN];

// Map linear pair index p -> (bi, bj) with bi <= bj.
__device__ __forceinline__ void decode_pair(int p, int& bi, int& bj) {
    const int C = 2 * NBLK + 1;                       // 257
    float disc = (float)(C * C - 8 * p);
    int x = (int)(((float)C - sqrtf(disc)) * 0.5f);
    if (x < 0) x = 0;
    while (x > 0 && x * (C - x) / 2 > p) x--;
    while ((x + 1) * (C - (x + 1)) / 2 <= p) x++;
    bi = x;
    bj = bi + (p - bi * (C - bi) / 2);
}

// ---------------------------------------------------------------------------
// Pass 1: per-tile-pair rowsums of s = relu((A + A^T)/2).
// Stage both tiles (U = A[bi-rows, bj-cols], L = A[bj-rows, bi-cols]) in smem.
//   rowsum(r) = sum_c relu((U[r][c] + L[c][r])/2)   -> slot bj, row gi0+r
//   colsum(c) = sum_r relu((U[r][c] + L[c][r])/2)   -> slot bi, row gj0+c
// 128 jobs x 2 halves = 256 threads; pure sequential scans, zero shuffles.
// All smem accesses are conflict-free with PAD=65 (banks = (r+c)%32 distinct).
// ---------------------------------------------------------------------------
__global__ __launch_bounds__(256) void rowsum_kernel(const float* __restrict__ A) {
    __shared__ float uSh[TILE][PAD];
    __shared__ float lSh[TILE][PAD];
    __shared__ float psum[2][2 * TILE];

    int bi, bj;
    decode_pair(blockIdx.x, bi, bj);
    const int tid = threadIdx.x;
    const int q = tid & 15;          // float4 column (16 per 64-wide row)
    const int w = tid >> 4;          // 0..15 base row
    const int gi0 = bi * TILE, gj0 = bj * TILE;

    // Vectorized, front-batched tile loads (LDG.128), scalar STS into padded smem.
    const float4* Au = (const float4*)(A + (size_t)gi0 * NN + gj0);
    const float4* Al = (const float4*)(A + (size_t)gj0 * NN + gi0);
    #pragma unroll
    for (int k = 0; k < 4; k++) {
        int r = w + 16 * k;
        float4 u = Au[(size_t)r * (NN / 4) + q];
        float4 l = Al[(size_t)r * (NN / 4) + q];
        uSh[r][4 * q + 0] = u.x; uSh[r][4 * q + 1] = u.y;
        uSh[r][4 * q + 2] = u.z; uSh[r][4 * q + 3] = u.w;
        lSh[r][4 * q + 0] = l.x; lSh[r][4 * q + 1] = l.y;
        lSh[r][4 * q + 2] = l.z; lSh[r][4 * q + 3] = l.w;
    }
    __syncthreads();

    const int jid = tid & 127;       // job id (0..63 row sums, 64..127 col sums)
    const int half = tid >> 7;       // each job split across 2 threads
    const int c0 = 32 * half;
    float acc = 0.0f;
    if (jid < TILE) {
        const int r = jid;
        #pragma unroll 8
        for (int c = c0; c < c0 + 32; c++)
            acc += fmaxf(0.5f * (uSh[r][c] + lSh[c][r]), 0.0f);
    } else {
        const int c = jid - TILE;
        #pragma unroll 8
        for (int r = c0; r < c0 + 32; r++)
            acc += fmaxf(0.5f * (uSh[r][c] + lSh[c][r]), 0.0f);
    }
    psum[half][jid] = acc;
    __syncthreads();

    if (tid < TILE) {
        g_partial[(size_t)bj * NN + gi0 + tid] = psum[0][tid] + psum[1][tid];
    } else if (tid < 2 * TILE && bi != bj) {
        const int c = tid - TILE;
        g_partial[(size_t)bi * NN + gj0 + c] = psum[0][tid] + psum[1][tid];
    }
}

// ---------------------------------------------------------------------------
// Pass 2: rowsum = 1 (self-loop) + sum of 128 partials; r_inv = rsqrt(rowsum).
// rowsum >= 1 always, so no inf handling needed.
// ---------------------------------------------------------------------------
__global__ void rinv_kernel() {
    int i = blockIdx.x * blockDim.x + threadIdx.x;
    float acc = 1.0f;
    #pragma unroll 8
    for (int s = 0; s < NBLK; s++)
        acc += g_partial[(size_t)s * NN + i];   // coalesced across threads
    g_rinv[i] = rsqrtf(acc);
}

// ---------------------------------------------------------------------------
// Pass 3: out[i][j] = r_inv[i] * (s + (i==j)) * r_inv[j].
// U read float4 from gmem, L staged in smem; upper tile written as STG.128,
// mirror tile transposed through smem and written as STG.128.
// ---------------------------------------------------------------------------
__global__ __launch_bounds__(256) void scale_kernel(const float* __restrict__ A,
                                                    float* __restrict__ out) {
    __shared__ float lSh[TILE][PAD];
    __shared__ float vSh[TILE][PAD];
    __shared__ float ri[TILE];
    __shared__ float rj[TILE];

    int bi, bj;
    decode_pair(blockIdx.x, bi, bj);
    const int tid = threadIdx.x;
    const int q = tid & 15;
    const int w = tid >> 4;
    const int gi0 = bi * TILE, gj0 = bj * TILE;
    const bool diag = (bi == bj);

    if (tid < TILE)            ri[tid] = g_rinv[gi0 + tid];
    else if (tid < 2 * TILE)   rj[tid - TILE] = g_rinv[gj0 + tid - TILE];

    const float4* Al = (const float4*)(A + (size_t)gj0 * NN + gi0);
    #pragma unroll
    for (int k = 0; k < 4; k++) {
        int r = w + 16 * k;
        float4 l = Al[(size_t)r * (NN / 4) + q];
        lSh[r][4 * q + 0] = l.x; lSh[r][4 * q + 1] = l.y;
        lSh[r][4 * q + 2] = l.z; lSh[r][4 * q + 3] = l.w;
    }
    __syncthreads();

    const float4* Au = (const float4*)(A + (size_t)gi0 * NN + gj0);
    float4* Ou = (float4*)(out + (size_t)gi0 * NN + gj0);
    #pragma unroll
    for (int k = 0; k < 4; k++) {
        const int i = w + 16 * k;
        float4 u = Au[(size_t)i * (NN / 4) + q];
        const float riv = ri[i];
        const int j0 = 4 * q;
        float4 v;
        {
            float s = fmaxf(0.5f * (u.x + lSh[j0 + 0][i]), 0.0f);
            if (diag && i == j0 + 0) s += 1.0f;
            v.x = riv * s * rj[j0 + 0];
        }
        {
            float s = fmaxf(0.5f * (u.y + lSh[j0 + 1][i]), 0.0f);
            if (diag && i == j0 + 1) s += 1.0f;
            v.y = riv * s * rj[j0 + 1];
        }
        {
            float s = fmaxf(0.5f * (u.z + lSh[j0 + 2][i]), 0.0f);
            if (diag && i == j0 + 2) s += 1.0f;
            v.z = riv * s * rj[j0 + 2];
        }
        {
            float s = fmaxf(0.5f * (u.w + lSh[j0 + 3][i]), 0.0f);
            if (diag && i == j0 + 3) s += 1.0f;
            v.w = riv * s * rj[j0 + 3];
        }
        Ou[(size_t)i * (NN / 4) + q] = v;
        vSh[i][j0 + 0] = v.x; vSh[i][j0 + 1] = v.y;
        vSh[i][j0 + 2] = v.z; vSh[i][j0 + 3] = v.w;
    }

    if (!diag) {
        __syncthreads();
        float4* Om = (float4*)(out + (size_t)gj0 * NN + gi0);
        #pragma unroll
        for (int k = 0; k < 4; k++) {
            const int r = w + 16 * k;
            float4 m;
            m.x = vSh[4 * q + 0][r];
            m.y = vSh[4 * q + 1][r];
            m.z = vSh[4 * q + 2][r];
            m.w = vSh[4 * q + 3][r];
            Om[(size_t)r * (NN / 4) + q] = m;
        }
    }
}

extern "C" void kernel_launch(void* const* d_in, const int* in_sizes, int n_in,
                              void* d_out, int out_size) {
    const float* A = (const float*)d_in[0];
    float* out = (float*)d_out;

    rowsum_kernel<<<NPAIRS, 256>>>(A);
    rinv_kernel<<<NN / 256, 256>>>();
    scale_kernel<<<NPAIRS, 256>>>(A, out);
}

// round 16
// speedup vs baseline: 1.4321x; 1.0847x over previous
#include <cuda_runtime.h>
#include <math.h>

#define NN     8192
#define TILE   64
#define NBLK   (NN / TILE)                 // 128
#define NPAIRS (NBLK * (NBLK + 1) / 2)     // 8256

// Deterministic partial rowsums: g_partial[slot][row], each (row,slot) written
// exactly once per launch (no atomics -> bit-identical every call).
__device__ float g_partial[(size_t)NBLK * NN];   // 4 MB scratch
__device__ float g_rinv[NN];

// Map linear pair index p -> (bi, bj) with bi <= bj.
__device__ __forceinline__ void decode_pair(int p, int& bi, int& bj) {
    const int C = 2 * NBLK + 1;                       // 257
    float disc = (float)(C * C - 8 * p);
    int x = (int)(((float)C - sqrtf(disc)) * 0.5f);
    if (x < 0) x = 0;
    while (x > 0 && x * (C - x) / 2 > p) x--;
    while ((x + 1) * (C - (x + 1)) / 2 <= p) x++;
    bi = x;
    bj = bi + (p - bi * (C - bi) / 2);
}

// ---- cp.async helpers (cg: L2-only, streaming) ----------------------------
__device__ __forceinline__ void cp_async16(void* smem_dst, const void* gmem_src) {
    unsigned saddr = (unsigned)__cvta_generic_to_shared(smem_dst);
    asm volatile("cp.async.cg.shared.global [%0], [%1], 16;"
                 :: "r"(saddr), "l"(gmem_src) : "memory");
}
#define CP_ASYNC_COMMIT() asm volatile("cp.async.commit_group;" ::: "memory")
#define CP_ASYNC_WAIT0()  asm volatile("cp.async.wait_group 0;" ::: "memory")

// ---- swizzled 64x64 tile layout (no pad; 16B-aligned float4 slots) --------
// Physical float index of logical (row, el): slot (el>>2) is XOR'd with row>>2.
__device__ __forceinline__ int swz_el(int row, int el) {
    return row * 64 + ((((el >> 2) ^ (row >> 2)) & 15) << 2) + (el & 3);
}
__device__ __forceinline__ int swz_slot(int row, int slot) {
    return row * 64 + (((slot ^ (row >> 2)) & 15) << 2);
}

// ---------------------------------------------------------------------------
// Pass 1: per-tile-pair rowsums of s = relu((A + A^T)/2), each element
// computed ONCE. Thread (q = tid&15, w = tid>>4) owns the 4x4 patch
// rows {w+16k}, cols {4q..4q+3}. U float4s live in registers (load mapping ==
// compute mapping); only L is staged (transposed access), via cp.async.
//   row partials  -> rp[q][r], reduced over 16 q's   -> slot bj
//   col partials  -> cpt[w][c], reduced over 16 w's  -> slot bi (symmetry)
// ---------------------------------------------------------------------------
__global__ __launch_bounds__(256) void rowsum_kernel(const float* __restrict__ A) {
    __shared__ float lSh[TILE * TILE];          // swizzled L tile (16 KB)
    __shared__ float rp[16][TILE + 1];          // rp[q][r]  row partials
    __shared__ float cpt[16][TILE + 1];         // cpt[w][c] col partials

    int bi, bj;
    decode_pair(blockIdx.x, bi, bj);
    const int tid = threadIdx.x;
    const int q = tid & 15, w = tid >> 4;
    const int gi0 = bi * TILE, gj0 = bj * TILE;

    const float4* Al = (const float4*)(A + (size_t)gj0 * NN + gi0);
    const float4* Au = (const float4*)(A + (size_t)gi0 * NN + gj0);

    // Stage L asynchronously (16B chunks into swizzled slots).
    #pragma unroll
    for (int k = 0; k < 4; k++) {
        int r = w + 16 * k;
        cp_async16(&lSh[swz_slot(r, q)], &Al[(size_t)r * (NN / 4) + q]);
    }
    CP_ASYNC_COMMIT();

    // U tile straight to registers (front-batched LDG.128, streaming).
    float4 uv[4];
    #pragma unroll
    for (int k = 0; k < 4; k++)
        uv[k] = __ldcs(&Au[(size_t)(w + 16 * k) * (NN / 4) + q]);

    CP_ASYNC_WAIT0();
    __syncthreads();

    float racc[4];
    float cacc[4] = {0.0f, 0.0f, 0.0f, 0.0f};
    #pragma unroll
    for (int k = 0; k < 4; k++) {
        const int r = w + 16 * k;
        // s(r, 4q+e) needs L[4q+e][r] (transposed read from swizzled lSh).
        float s0 = fmaxf(0.5f * (uv[k].x + lSh[swz_el(4 * q + 0, r)]), 0.0f);
        float s1 = fmaxf(0.5f * (uv[k].y + lSh[swz_el(4 * q + 1, r)]), 0.0f);
        float s2 = fmaxf(0.5f * (uv[k].z + lSh[swz_el(4 * q + 2, r)]), 0.0f);
        float s3 = fmaxf(0.5f * (uv[k].w + lSh[swz_el(4 * q + 3, r)]), 0.0f);
        racc[k] = (s0 + s1) + (s2 + s3);
        cacc[0] += s0; cacc[1] += s1; cacc[2] += s2; cacc[3] += s3;
    }
    #pragma unroll
    for (int k = 0; k < 4; k++) rp[q][w + 16 * k] = racc[k];
    #pragma unroll
    for (int e = 0; e < 4; e++) cpt[w][4 * q + e] = cacc[e];
    __syncthreads();

    if (tid < TILE) {
        float acc = 0.0f;
        #pragma unroll
        for (int t = 0; t < 16; t++) acc += rp[t][tid];
        g_partial[(size_t)bj * NN + gi0 + tid] = acc;
    } else if (tid < 2 * TILE && bi != bj) {
        const int c = tid - TILE;
        float acc = 0.0f;
        #pragma unroll
        for (int t = 0; t < 16; t++) acc += cpt[t][c];
        g_partial[(size_t)bi * NN + gj0 + c] = acc;
    }
}

// ---------------------------------------------------------------------------
// Pass 2: rowsum = 1 (self-loop) + sum of 128 partials; r_inv = rsqrt(rowsum).
// 128 CTAs (one per 64 rows); 4 thread-groups each sum 32 slots, smem-combined.
// rowsum >= 1 always, so no inf handling needed.
// ---------------------------------------------------------------------------
__global__ __launch_bounds__(256) void rinv_kernel() {
    __shared__ float red[4][TILE];
    const int lr = threadIdx.x & 63;
    const int sg = threadIdx.x >> 6;             // 0..3
    const int r = blockIdx.x * TILE + lr;
    float acc = 0.0f;
    #pragma unroll 8
    for (int s = sg * 32; s < sg * 32 + 32; s++)
        acc += g_partial[(size_t)s * NN + r];    // coalesced (fixed s, 64 rows)
    red[sg][lr] = acc;
    __syncthreads();
    if (threadIdx.x < TILE)
        g_rinv[blockIdx.x * TILE + threadIdx.x] =
            rsqrtf(1.0f + ((red[0][threadIdx.x] + red[1][threadIdx.x]) +
                           (red[2][threadIdx.x] + red[3][threadIdx.x])));
}

// ---------------------------------------------------------------------------
// Pass 3: out[i][j] = r_inv[i] * (s + (i==j)) * r_inv[j].
// U to regs (streaming), L staged via cp.async (swizzled), upper tile written
// as STG.128, mirror tile transposed through a swizzled smem buffer.
// ---------------------------------------------------------------------------
__global__ __launch_bounds__(256) void scale_kernel(const float* __restrict__ A,
                                                    float* __restrict__ out) {
    __shared__ float lSh[TILE * TILE];
    __shared__ float vSh[TILE * TILE];
    __shared__ float ri[TILE];
    __shared__ float rj[TILE];

    int bi, bj;
    decode_pair(blockIdx.x, bi, bj);
    const int tid = threadIdx.x;
    const int q = tid & 15, w = tid >> 4;
    const int gi0 = bi * TILE, gj0 = bj * TILE;
    const bool diag = (bi == bj);

    const float4* Al = (const float4*)(A + (size_t)gj0 * NN + gi0);
    #pragma unroll
    for (int k = 0; k < 4; k++) {
        int r = w + 16 * k;
        cp_async16(&lSh[swz_slot(r, q)], &Al[(size_t)r * (NN / 4) + q]);
    }
    CP_ASYNC_COMMIT();

    if (tid < TILE)          ri[tid] = g_rinv[gi0 + tid];
    else if (tid < 2 * TILE) rj[tid - TILE] = g_rinv[gj0 + tid - TILE];

    const float4* Au = (const float4*)(A + (size_t)gi0 * NN + gj0);
    float4 uv[4];
    #pragma unroll
    for (int k = 0; k < 4; k++)
        uv[k] = __ldcs(&Au[(size_t)(w + 16 * k) * (NN / 4) + q]);

    CP_ASYNC_WAIT0();
    __syncthreads();

    float4* Ou = (float4*)(out + (size_t)gi0 * NN + gj0);
    const int j0 = 4 * q;
    #pragma unroll
    for (int k = 0; k < 4; k++) {
        const int i = w + 16 * k;
        const float riv = ri[i];
        float4 v;
        {
            float s = fmaxf(0.5f * (uv[k].x + lSh[swz_el(j0 + 0, i)]), 0.0f);
            if (diag && i == j0 + 0) s += 1.0f;
            v.x = riv * s * rj[j0 + 0];
        }
        {
            float s = fmaxf(0.5f * (uv[k].y + lSh[swz_el(j0 + 1, i)]), 0.0f);
            if (diag && i == j0 + 1) s += 1.0f;
            v.y = riv * s * rj[j0 + 1];
        }
        {
            float s = fmaxf(0.5f * (uv[k].z + lSh[swz_el(j0 + 2, i)]), 0.0f);
            if (diag && i == j0 + 2) s += 1.0f;
            v.z = riv * s * rj[j0 + 2];
        }
        {
            float s = fmaxf(0.5f * (uv[k].w + lSh[swz_el(j0 + 3, i)]), 0.0f);
            if (diag && i == j0 + 3) s += 1.0f;
            v.w = riv * s * rj[j0 + 3];
        }
        __stcs(&Ou[(size_t)i * (NN / 4) + q], v);
        // stash for the mirror (STS.128 into swizzled slot: conflict-free)
        *(float4*)&vSh[swz_slot(i, q)] = v;
    }

    if (!diag) {
        __syncthreads();
        float4* Om = (float4*)(out + (size_t)gj0 * NN + gi0);
        #pragma unroll
        for (int k = 0; k < 4; k++) {
            const int r = w + 16 * k;
            float4 m;
            m.x = vSh[swz_el(j0 + 0, r)];
            m.y = vSh[swz_el(j0 + 1, r)];
            m.z = vSh[swz_el(j0 + 2, r)];
            m.w = vSh[swz_el(j0 + 3, r)];
            __stcs(&Om[(size_t)r * (NN / 4) + q], m);
        }
    }
}

extern "C" void kernel_launch(void* const* d_in, const int* in_sizes, int n_in,
                              void* d_out, int out_size) {
    const float* A = (const float*)d_in[0];
    float* out = (float*)d_out;

    rowsum_kernel<<<NPAIRS, 256>>>(A);
    rinv_kernel<<<NBLK, 256>>>();
    scale_kernel<<<NPAIRS, 256>>>(A, out);
}

// round 17
// speedup vs baseline: 1.4364x; 1.0030x over previous
#include <cuda_runtime.h>
#include <math.h>

#define NN     8192
#define TILE   64
#define NBLK   (NN / TILE)                 // 128
#define NPAIRS (NBLK * (NBLK + 1) / 2)     // 8256

// Deterministic partial rowsums: g_partial[slot][row], each (row,slot) written
// exactly once per launch (no atomics -> bit-identical every call).
__device__ float g_partial[(size_t)NBLK * NN];   // 4 MB scratch
__device__ float g_rinv[NN];

// Map linear pair index p -> (bi, bj) with bi <= bj.
__device__ __forceinline__ void decode_pair(int p, int& bi, int& bj) {
    const int C = 2 * NBLK + 1;                       // 257
    float disc = (float)(C * C - 8 * p);
    int x = (int)(((float)C - sqrtf(disc)) * 0.5f);
    if (x < 0) x = 0;
    while (x > 0 && x * (C - x) / 2 > p) x--;
    while ((x + 1) * (C - (x + 1)) / 2 <= p) x++;
    bi = x;
    bj = bi + (p - bi * (C - bi) / 2);
}

// ---- cp.async helpers (cg: L2-only, streaming) ----------------------------
__device__ __forceinline__ void cp_async16(void* smem_dst, const void* gmem_src) {
    unsigned saddr = (unsigned)__cvta_generic_to_shared(smem_dst);
    asm volatile("cp.async.cg.shared.global [%0], [%1], 16;"
                 :: "r"(saddr), "l"(gmem_src) : "memory");
}
#define CP_ASYNC_COMMIT() asm volatile("cp.async.commit_group;" ::: "memory")
#define CP_ASYNC_WAIT0()  asm volatile("cp.async.wait_group 0;" ::: "memory")

// ---- swizzled 64x64 tile layout (no pad; 16B-aligned float4 slots) --------
// Physical float index of logical (row, el): slot (el>>2) is XOR'd with row>>2.
__device__ __forceinline__ int swz_el(int row, int el) {
    return row * 64 + ((((el >> 2) ^ (row >> 2)) & 15) << 2) + (el & 3);
}
__device__ __forceinline__ int swz_slot(int row, int slot) {
    return row * 64 + (((slot ^ (row >> 2)) & 15) << 2);
}

// ---------------------------------------------------------------------------
// Pass 1: per-tile-pair rowsums of s = relu((A + A^T)/2), each element
// computed ONCE. Thread (q = tid&15, w = tid>>4) owns the 4x4 patch
// rows {w+16k}, cols {4q..4q+3}. U float4s live in registers (load mapping ==
// compute mapping); only L is staged (transposed access), via cp.async.
//   row partials  -> rp[q][r], reduced over 16 q's   -> slot bj
//   col partials  -> cpt[w][c], reduced over 16 w's  -> slot bi (symmetry)
// ---------------------------------------------------------------------------
__global__ __launch_bounds__(256) void rowsum_kernel(const float* __restrict__ A) {
    __shared__ float lSh[TILE * TILE];          // swizzled L tile (16 KB)
    __shared__ float rp[16][TILE + 1];          // rp[q][r]  row partials
    __shared__ float cpt[16][TILE + 1];         // cpt[w][c] col partials

    int bi, bj;
    decode_pair(blockIdx.x, bi, bj);
    const int tid = threadIdx.x;
    const int q = tid & 15, w = tid >> 4;
    const int gi0 = bi * TILE, gj0 = bj * TILE;

    const float4* Al = (const float4*)(A + (size_t)gj0 * NN + gi0);
    const float4* Au = (const float4*)(A + (size_t)gi0 * NN + gj0);

    // Stage L asynchronously (16B chunks into swizzled slots).
    #pragma unroll
    for (int k = 0; k < 4; k++) {
        int r = w + 16 * k;
        cp_async16(&lSh[swz_slot(r, q)], &Al[(size_t)r * (NN / 4) + q]);
    }
    CP_ASYNC_COMMIT();

    // U tile straight to registers (front-batched LDG.128, streaming).
    float4 uv[4];
    #pragma unroll
    for (int k = 0; k < 4; k++)
        uv[k] = __ldcs(&Au[(size_t)(w + 16 * k) * (NN / 4) + q]);

    CP_ASYNC_WAIT0();
    __syncthreads();

    float racc[4];
    float cacc[4] = {0.0f, 0.0f, 0.0f, 0.0f};
    #pragma unroll
    for (int k = 0; k < 4; k++) {
        const int r = w + 16 * k;
        // s(r, 4q+e) needs L[4q+e][r] (transposed read from swizzled lSh).
        float s0 = fmaxf(0.5f * (uv[k].x + lSh[swz_el(4 * q + 0, r)]), 0.0f);
        float s1 = fmaxf(0.5f * (uv[k].y + lSh[swz_el(4 * q + 1, r)]), 0.0f);
        float s2 = fmaxf(0.5f * (uv[k].z + lSh[swz_el(4 * q + 2, r)]), 0.0f);
        float s3 = fmaxf(0.5f * (uv[k].w + lSh[swz_el(4 * q + 3, r)]), 0.0f);
        racc[k] = (s0 + s1) + (s2 + s3);
        cacc[0] += s0; cacc[1] += s1; cacc[2] += s2; cacc[3] += s3;
    }
    #pragma unroll
    for (int k = 0; k < 4; k++) rp[q][w + 16 * k] = racc[k];
    #pragma unroll
    for (int e = 0; e < 4; e++) cpt[w][4 * q + e] = cacc[e];
    __syncthreads();

    if (tid < TILE) {
        float acc = 0.0f;
        #pragma unroll
        for (int t = 0; t < 16; t++) acc += rp[t][tid];
        g_partial[(size_t)bj * NN + gi0 + tid] = acc;
    } else if (tid < 2 * TILE && bi != bj) {
        const int c = tid - TILE;
        float acc = 0.0f;
        #pragma unroll
        for (int t = 0; t < 16; t++) acc += cpt[t][c];
        g_partial[(size_t)bi * NN + gj0 + c] = acc;
    }
}

// ---------------------------------------------------------------------------
// Pass 2: rowsum = 1 (self-loop) + sum of 128 partials; r_inv = rsqrt(rowsum).
// 128 CTAs (one per 64 rows); 4 thread-groups each sum 32 slots, smem-combined.
// rowsum >= 1 always, so no inf handling needed.
// ---------------------------------------------------------------------------
__global__ __launch_bounds__(256) void rinv_kernel() {
    __shared__ float red[4][TILE];
    const int lr = threadIdx.x & 63;
    const int sg = threadIdx.x >> 6;             // 0..3
    const int r = blockIdx.x * TILE + lr;
    float acc = 0.0f;
    #pragma unroll 8
    for (int s = sg * 32; s < sg * 32 + 32; s++)
        acc += g_partial[(size_t)s * NN + r];    // coalesced (fixed s, 64 rows)
    red[sg][lr] = acc;
    __syncthreads();
    if (threadIdx.x < TILE)
        g_rinv[blockIdx.x * TILE + threadIdx.x] =
            rsqrtf(1.0f + ((red[0][threadIdx.x] + red[1][threadIdx.x]) +
                           (red[2][threadIdx.x] + red[3][threadIdx.x])));
}

// ---------------------------------------------------------------------------
// Pass 3: out[i][j] = r_inv[i] * (s + (i==j)) * r_inv[j].
// U to regs (streaming), L staged via cp.async (swizzled), upper tile written
// as STG.128, mirror tile transposed through a swizzled smem buffer.
// ---------------------------------------------------------------------------
__global__ __launch_bounds__(256) void scale_kernel(const float* __restrict__ A,
                                                    float* __restrict__ out) {
    __shared__ float lSh[TILE * TILE];
    __shared__ float vSh[TILE * TILE];
    __shared__ float ri[TILE];
    __shared__ float rj[TILE];

    int bi, bj;
    decode_pair(blockIdx.x, bi, bj);
    const int tid = threadIdx.x;
    const int q = tid & 15, w = tid >> 4;
    const int gi0 = bi * TILE, gj0 = bj * TILE;
    const bool diag = (bi == bj);

    const float4* Al = (const float4*)(A + (size_t)gj0 * NN + gi0);
    #pragma unroll
    for (int k = 0; k < 4; k++) {
        int r = w + 16 * k;
        cp_async16(&lSh[swz_slot(r, q)], &Al[(size_t)r * (NN / 4) + q]);
    }
    CP_ASYNC_COMMIT();

    if (tid < TILE)          ri[tid] = g_rinv[gi0 + tid];
    else if (tid < 2 * TILE) rj[tid - TILE] = g_rinv[gj0 + tid - TILE];

    const float4* Au = (const float4*)(A + (size_t)gi0 * NN + gj0);
    float4 uv[4];
    #pragma unroll
    for (int k = 0; k < 4; k++)
        uv[k] = __ldcs(&Au[(size_t)(w + 16 * k) * (NN / 4) + q]);

    CP_ASYNC_WAIT0();
    __syncthreads();

    float4* Ou = (float4*)(out + (size_t)gi0 * NN + gj0);
    const int j0 = 4 * q;
    #pragma unroll
    for (int k = 0; k < 4; k++) {
        const int i = w + 16 * k;
        const float riv = ri[i];
        float4 v;
        {
            float s = fmaxf(0.5f * (uv[k].x + lSh[swz_el(j0 + 0, i)]), 0.0f);
            if (diag && i == j0 + 0) s += 1.0f;
            v.x = riv * s * rj[j0 + 0];
        }
        {
            float s = fmaxf(0.5f * (uv[k].y + lSh[swz_el(j0 + 1, i)]), 0.0f);
            if (diag && i == j0 + 1) s += 1.0f;
            v.y = riv * s * rj[j0 + 1];
        }
        {
            float s = fmaxf(0.5f * (uv[k].z + lSh[swz_el(j0 + 2, i)]), 0.0f);
            if (diag && i == j0 + 2) s += 1.0f;
            v.z = riv * s * rj[j0 + 2];
        }
        {
            float s = fmaxf(0.5f * (uv[k].w + lSh[swz_el(j0 + 3, i)]), 0.0f);
            if (diag && i == j0 + 3) s += 1.0f;
            v.w = riv * s * rj[j0 + 3];
        }
        __stcs(&Ou[(size_t)i * (NN / 4) + q], v);
        // stash for the mirror (STS.128 into swizzled slot: conflict-free)
        *(float4*)&vSh[swz_slot(i, q)] = v;
    }

    if (!diag) {
        __syncthreads();
        float4* Om = (float4*)(out + (size_t)gj0 * NN + gi0);
        #pragma unroll
        for (int k = 0; k < 4; k++) {
            const int r = w + 16 * k;
            float4 m;
            m.x = vSh[swz_el(j0 + 0, r)];
            m.y = vSh[swz_el(j0 + 1, r)];
            m.z = vSh[swz_el(j0 + 2, r)];
            m.w = vSh[swz_el(j0 + 3, r)];
            __stcs(&Om[(size_t)r * (NN / 4) + q], m);
        }
    }
}

extern "C" void kernel_launch(void* const* d_in, const int* in_sizes, int n_in,
                              void* d_out, int out_size) {
    const float* A = (const float*)d_in[0];
    float* out = (float*)d_out;

    rowsum_kernel<<<NPAIRS, 256>>>(A);
    rinv_kernel<<<NBLK, 256>>>();
    scale_kernel<<<NPAIRS, 256>>>(A, out);
}